// round 4
// baseline (speedup 1.0000x reference)
#include <cuda_runtime.h>
#include <cstdint>

#define IMG_W   1024
#define IMG_H   1024
#define IMG_PIX (IMG_W * IMG_H)
#define N_IMG   32
#define TOTAL_F ((size_t)N_IMG * IMG_PIX)     // floats per tensor
#define SMOOTH  1e-5
#define BAND    256
#define SW_OUT  64                 // output float4 groups per strip (256 cols)
#define SW_IN   72                 // loaded groups per strip (288 cols, halo 16 each side)
#define SWID    (SW_IN * 4)        // 288 floats per smem level row
#define NTHR    144                // 2 row-slots x 72 groups
#define SKELR   30                 // skel ring rows (live window = 26 for T=9)

// Scratch: 64-image (2-tensor) buffers. No cudaMalloc allowed.
__device__ float g_bufA[2 * N_IMG * IMG_PIX];
__device__ float g_bufB[2 * N_IMG * IMG_PIX];
__device__ float g_skel[2 * N_IMG * IMG_PIX];
__device__ double g_sums[4];

__device__ __forceinline__ float4 ld4(const float* p) { return *(const float4*)p; }
__device__ __forceinline__ void st4(float* p, float4 v) { *(float4*)p = v; }
__device__ __forceinline__ float mn3(float a, float b, float c) { return fminf(a, fminf(b, c)); }
__device__ __forceinline__ float mx3(float a, float b, float c) { return fmaxf(a, fmaxf(b, c)); }
__device__ __forceinline__ int w6(int v) {            // v in [0, 17] -> v mod 6
    v -= (v >= 12) ? 12 : 0;
    v -= (v >= 6) ? 6 : 0;
    return v;
}
__device__ __forceinline__ void skel_upd(float4& s, const float4& d) {
    s.x += fmaxf(fmaf(-s.x, d.x, d.x), 0.0f);
    s.y += fmaxf(fmaf(-s.y, d.y, d.y), 0.0f);
    s.z += fmaxf(fmaf(-s.z, d.z, d.z), 0.0f);
    s.w += fmaxf(fmaf(-s.w, d.w, d.w), 0.0f);
}

// Skewed erosion tower. Level j (1..T) computes rows Y-3j, Y-3j+1 at sweep step Y,
// reading only previous-step data -> one barrier covers all levels.
// delta_j (j=0..T-1) at rows Y-3j-4, Y-3j-3 after a second barrier.
// Rings: 6 rows per level (all accesses span <= 6 consecutive rows).
template <int T, bool INIT, bool WRITE_E>
__global__ __launch_bounds__(NTHR)
void tower(const float* __restrict__ p0, const float* __restrict__ p1,
           float* __restrict__ eout, float* __restrict__ gskel)
{
    extern __shared__ float sm[];            // (T+1) level rings of 6 rows x 288 floats
    float* const skelr = sm + (T + 1) * 6 * SWID;  // + SKELR rows x 256 floats

    const int tid = threadIdx.x;
    const int rs  = (tid >= SW_IN) ? 1 : 0;
    const int lg  = tid - rs * SW_IN;        // local group 0..71
    const int strip = blockIdx.x;
    const int y0  = blockIdx.y * BAND, y1 = y0 + BAND;
    const int n   = blockIdx.z;              // 0..63 (tensor*32 + image)
    const float INF  = __int_as_float(0x7f800000);
    const float NINF = -INF;

    const float* src = (n < N_IMG) ? (p0 + (size_t)n * IMG_PIX)
                                   : (p1 + (size_t)(n - N_IMG) * IMG_PIX);
    const float4* in4   = (const float4*)src;
    float4*       eout4 = (float4*)(WRITE_E ? (eout + (size_t)n * IMG_PIX) : nullptr);
    float4*       skel4 = (float4*)(gskel + (size_t)n * IMG_PIX);

    const int gbase = strip * SW_OUT;        // global output group base
    const int gx0   = gbase * 4;             // global output col base
    const int x4    = lg * 4;

    // Prefill level rings with +inf (out-of-image / pre-sweep padding)
    {
        const float4 inf4 = make_float4(INF, INF, INF, INF);
        float4* s4 = (float4*)sm;
        for (int i = tid; i < (T + 1) * 6 * SW_IN; i += NTHR) s4[i] = inf4;
    }
    __syncthreads();

    const int Ys = y0 - T - 2;
    const int Ye = y1 + 3 * (T - 1) + 4;
    for (int Y = Ys; Y <= Ye; Y += 2) {
        const int ym = (int)((unsigned)(Y + 6000) % 6u);

        // ---- Phase 1: load row (Y+rs) + all erosion levels (prev-step reads only)
        {
            const int row = Y + rs;
            const int gg  = gbase - 4 + lg;                 // global group of this load
            float4 v = make_float4(INF, INF, INF, INF);
            if (row >= 0 && row < IMG_H && gg >= 0 && gg < IMG_W / 4)
                v = in4[row * (IMG_W / 4) + gg];
            st4(sm + w6(ym + rs) * SWID + x4, v);
        }
#pragma unroll
        for (int j = 1; j <= T; ++j) {
            const int dj = ((j & 1) ? 3 : 0) + rs;          // (rs - 3j) mod 6
            const int su = w6(ym + dj + 5);
            const int sc = w6(ym + dj);
            const int sd = w6(ym + dj + 1);
            const float* L  = sm + (j - 1) * 6 * SWID;
            const float* ru = L + su * SWID;
            const float* rc = L + sc * SWID;
            const float* rd = L + sd * SWID;
            const float4 u = ld4(ru + x4);
            const float4 c = ld4(rc + x4);
            const float4 d = ld4(rd + x4);
            const float cl = (lg == 0)         ? INF : rc[x4 - 1];
            const float cr = (lg == SW_IN - 1) ? INF : rc[x4 + 4];
            float4 o;
            o.x = fminf(mn3(u.x, c.x, d.x), fminf(cl,  c.y));
            o.y = fminf(mn3(u.y, c.y, d.y), fminf(c.x, c.z));
            o.z = fminf(mn3(u.z, c.z, d.z), fminf(c.y, c.w));
            o.w = fminf(mn3(u.w, c.w, d.w), fminf(c.z, cr));
            st4(sm + (j * 6 + sc) * SWID + x4, o);
            if (WRITE_E && j == T) {
                const int r = Y - 3 * T + rs;
                if (r >= y0 && r < y1 && lg >= 4 && lg < 4 + SW_OUT)
                    eout4[r * (IMG_W / 4) + gbase + (lg - 4)] = o;
            }
        }
        __syncthreads();

        // ---- Phase 2: deltas + skel recurrence. Items: (j, row-slot, output group)
        for (int idx = tid; idx < T * 128; idx += NTHR) {
            const int j  = idx >> 7;
            const int rr = (idx >> 6) & 1;
            const int og = idx & 63;
            const int y  = Y - 3 * j - 4 + rr;
            if (y < y0 || y >= y1) continue;

            const int lx = (og + 4) * 4;                    // local float col
            const int bse = ym + ((j & 1) ? 3 : 0) + 2 + rr; // (y) mod 6 offset
            const int sb  = w6(bse);
            const int sa  = w6(bse + 5);
            const int sc2 = w6(bse + 1);
            const float* Lb = sm + (j + 1) * 6 * SWID;
            const float* ra = Lb + sa * SWID;
            const float* rb = Lb + sb * SWID;
            const float* rc = Lb + sc2 * SWID;
            float4 a = ld4(ra + lx);
            float4 b = ld4(rb + lx);
            float4 c = ld4(rc + lx);
            float al = ra[lx - 1], bl = rb[lx - 1], cl = rc[lx - 1];
            float ar = ra[lx + 4], br = rb[lx + 4], cr = rc[lx + 4];
            if (y == 0)         { a = make_float4(NINF, NINF, NINF, NINF); al = NINF; ar = NINF; }
            if (y == IMG_H - 1) { c = make_float4(NINF, NINF, NINF, NINF); cl = NINF; cr = NINF; }
            const int gcol = gx0 + og * 4;
            if (gcol == 0)            { al = NINF; bl = NINF; cl = NINF; }
            if (gcol + 4 == IMG_W)    { ar = NINF; br = NINF; cr = NINF; }

            float4 vm;
            vm.x = mx3(a.x, b.x, c.x);
            vm.y = mx3(a.y, b.y, c.y);
            vm.z = mx3(a.z, b.z, c.z);
            vm.w = mx3(a.w, b.w, c.w);
            const float vl = mx3(al, bl, cl);
            const float vr = mx3(ar, br, cr);
            float4 op;
            op.x = fmaxf(vm.x, fmaxf(vl,   vm.y));
            op.y = fmaxf(vm.y, fmaxf(vm.x, vm.z));
            op.z = fmaxf(vm.z, fmaxf(vm.y, vm.w));
            op.w = fmaxf(vm.w, fmaxf(vm.z, vr));

            const float4 e = ld4(sm + (j * 6 + sb) * SWID + lx);
            float4 dl;
            dl.x = fmaxf(e.x - op.x, 0.0f);
            dl.y = fmaxf(e.y - op.y, 0.0f);
            dl.z = fmaxf(e.z - op.z, 0.0f);
            dl.w = fmaxf(e.w - op.w, 0.0f);

            float* srow = skelr + (y % SKELR) * (SW_OUT * 4) + og * 4;
            float4 s;
            if (j == 0) {
                if (INIT) s = make_float4(0.0f, 0.0f, 0.0f, 0.0f);
                else      s = skel4[y * (IMG_W / 4) + gbase + og];
            } else {
                s = ld4(srow);
            }
            skel_upd(s, dl);
            if (j == T - 1) skel4[y * (IMG_W / 4) + gbase + og] = s;
            else            st4(srow, s);
        }
        __syncthreads();
    }
}

__global__ void zero_sums(double* sums) {
    if (threadIdx.x < 4) sums[threadIdx.x] = 0.0;
}

// blockIdx.y = tensor t. sums[2t] += sum(skel_t * other_t); sums[2t+1] += sum(skel_t).
__global__ __launch_bounds__(256) void reduce_skel(const float* __restrict__ skel,
                                                   const float* __restrict__ target,
                                                   const float* __restrict__ inputs,
                                                   double* __restrict__ sums) {
    const int t = blockIdx.y;
    const float4* s4 = (const float4*)(skel + (size_t)t * TOTAL_F);
    const float4* o4 = (const float4*)((t == 0) ? target : inputs);
    const size_t n4 = TOTAL_F / 4;

    float acc_p = 0.0f, acc_s = 0.0f;
    const size_t stride = (size_t)gridDim.x * blockDim.x;
    for (size_t i = (size_t)blockIdx.x * blockDim.x + threadIdx.x; i < n4; i += stride) {
        const float4 a = s4[i];
        const float4 b = o4[i];
        acc_p += a.x * b.x + a.y * b.y + a.z * b.z + a.w * b.w;
        acc_s += a.x + a.y + a.z + a.w;
    }
#pragma unroll
    for (int off = 16; off > 0; off >>= 1) {
        acc_p += __shfl_down_sync(0xffffffffu, acc_p, off);
        acc_s += __shfl_down_sync(0xffffffffu, acc_s, off);
    }
    if ((threadIdx.x & 31) == 0) {
        atomicAdd(&sums[2 * t],     (double)acc_p);
        atomicAdd(&sums[2 * t + 1], (double)acc_s);
    }
}

__global__ void finalize_cldice(const double* __restrict__ sums, float* __restrict__ out) {
    const double tprec = (sums[0] + SMOOTH) / (sums[1] + SMOOTH);
    const double tsens = (sums[2] + SMOOTH) / (sums[3] + SMOOTH);
    out[0] = (float)(1.0 - 2.0 * (tprec * tsens) / (tprec + tsens));
}

extern "C" void kernel_launch(void* const* d_in, const int* in_sizes, int n_in,
                              void* d_out, int out_size) {
    const float* target = (const float*)d_in[0];
    const float* inputs = (const float*)d_in[1];
    float* out = (float*)d_out;

    static float* bufA = nullptr;
    static float* bufB = nullptr;
    static float* skel = nullptr;
    static double* sums = nullptr;
    static bool attr_done = false;
    if (!bufA) {
        cudaGetSymbolAddress((void**)&bufA, g_bufA);
        cudaGetSymbolAddress((void**)&bufB, g_bufB);
        cudaGetSymbolAddress((void**)&skel, g_skel);
        cudaGetSymbolAddress((void**)&sums, g_sums);
    }
    const int SM9 = (10 * 6 * SWID + SKELR * SW_OUT * 4) * 4;  // 99,840 B
    const int SM8 = (9  * 6 * SWID + SKELR * SW_OUT * 4) * 4;  // 92,928 B
    if (!attr_done) {
        cudaFuncSetAttribute(tower<9, true,  true >, cudaFuncAttributeMaxDynamicSharedMemorySize, SM9);
        cudaFuncSetAttribute(tower<9, false, true >, cudaFuncAttributeMaxDynamicSharedMemorySize, SM9);
        cudaFuncSetAttribute(tower<8, false, false>, cudaFuncAttributeMaxDynamicSharedMemorySize, SM8);
        attr_done = true;
    }

    const dim3 grid(IMG_W / (SW_OUT * 4), IMG_H / BAND, 2 * N_IMG);  // (4, 4, 64)
    const dim3 block(NTHR);

    zero_sums<<<1, 32>>>(sums);

    // E levels 0..26, deltas 0..25, both tensors per launch (z = tensor*32+img)
    tower<9, true,  true ><<<grid, block, SM9>>>(inputs, target, bufA, skel);
    tower<9, false, true ><<<grid, block, SM9>>>(bufA, bufA + TOTAL_F, bufB, skel);
    tower<8, false, false><<<grid, block, SM8>>>(bufB, bufB + TOTAL_F, nullptr, skel);

    reduce_skel<<<dim3(1024, 2), 256>>>(skel, target, inputs, sums);
    finalize_cldice<<<1, 1>>>(sums, out);
}

// round 5
// speedup vs baseline: 1.7357x; 1.7357x over previous
#include <cuda_runtime.h>
#include <cstdint>

#define IMG_W   1024
#define IMG_H   1024
#define IMG_PIX (IMG_W * IMG_H)
#define N_IMG   32
#define TOTAL_F ((size_t)N_IMG * IMG_PIX)
#define SMOOTH  1e-5
#define FULLM   0xffffffffu
#define BANDS   2
#define BROWS   (IMG_H / BANDS)       // 512
#define STRIPS  10                    // output 104 cols each (last 88)
#define NSTEPS  (BROWS + 22)          // 534, multiple of 3

// Scratch (no cudaMalloc allowed)
__device__ float g_bufA[2 * N_IMG * IMG_PIX];
__device__ float g_bufB[2 * N_IMG * IMG_PIX];
__device__ float g_skel[2 * N_IMG * IMG_PIX];
__device__ double g_sums[4];

__device__ __forceinline__ float4 ld4(const float* p) { return *(const float4*)p; }
__device__ __forceinline__ void st4(float* p, float4 v) { *(float4*)p = v; }

__device__ __forceinline__ void skel_upd(float4& s, const float4& d) {
    s.x += fmaxf(fmaf(-s.x, d.x, d.x), 0.0f);
    s.y += fmaxf(fmaf(-s.y, d.y, d.y), 0.0f);
    s.z += fmaxf(fmaf(-s.z, d.z, d.z), 0.0f);
    s.w += fmaxf(fmaf(-s.w, d.w, d.w), 0.0f);
}

// One sweep step at row Y, ring slot U (static via unroll-3).
// Ring invariant after step Y: L[j][U] = level-j row (Y-j); slot (U+2)%3 = row-1; (U+1)%3 = row-2.
template <int T, int U, bool INIT, bool WRITE_E>
__device__ __forceinline__ void do_step(
    int Y, float4 (&L)[T + 1][3],
    const float4* __restrict__ in4, float4* __restrict__ eout4,
    float4* __restrict__ skel4, float* __restrict__ ring,
    int lane, int gq, bool loadok, bool outok, bool ledge, bool redge,
    int b0, int b1)
{
    const float INF  = __int_as_float(0x7f800000);
    const float NINF = -INF;
    constexpr int u  = U;
    constexpr int h1 = (U + 2) % 3;   // row (r) for level j-1 center
    constexpr int h2 = (U + 1) % 3;

    // Load input row Y into level 0 (+inf outside image)
    {
        float4 v = make_float4(INF, INF, INF, INF);
        if (Y >= 0 && Y < IMG_H && loadok) v = in4[Y * 256 + gq];
        L[0][u] = v;
    }

    // Erosion levels: level j computes row r = Y - j from level j-1 rows r-1..r+1
#pragma unroll
    for (int j = 1; j <= T; ++j) {
        const int r = Y - j;
        const float4 up = L[j - 1][h2];   // r-1
        const float4 ce = L[j - 1][h1];   // r
        const float4 dn = L[j - 1][u];    // r+1
        const float cl = __shfl_up_sync(FULLM, ce.w, 1);
        const float cr = __shfl_down_sync(FULLM, ce.x, 1);
        float4 o;
        o.x = fminf(fminf(fminf(up.x, dn.x), fminf(cl,   ce.y)), ce.x);
        o.y = fminf(fminf(fminf(up.y, dn.y), fminf(ce.x, ce.z)), ce.y);
        o.z = fminf(fminf(fminf(up.z, dn.z), fminf(ce.y, ce.w)), ce.z);
        o.w = fminf(fminf(fminf(up.w, dn.w), fminf(ce.z, cr  )), ce.w);
        if (r < 0 || r >= IMG_H) o = make_float4(INF, INF, INF, INF);
        L[j][u] = o;
        if (WRITE_E && j == T) {
            if (r >= b0 && r < b1 && outok) eout4[r * 256 + gq] = o;
        }
    }

    // Deltas: delta_k at row y = Y - k - 2, uses E_k[y] and dilate(E_{k+1})[y]
#pragma unroll
    for (int k = 0; k < T; ++k) {
        const int y = Y - k - 2;
        if (y < b0 || y >= b1) continue;

        float4 a = L[k + 1][h2];   // y-1
        float4 b = L[k + 1][h1];   // y
        float4 c = L[k + 1][u];    // y+1
        if (y == 0)         a = make_float4(NINF, NINF, NINF, NINF);
        if (y == IMG_H - 1) c = make_float4(NINF, NINF, NINF, NINF);

        float4 vm;
        vm.x = fmaxf(a.x, fmaxf(b.x, c.x));
        vm.y = fmaxf(a.y, fmaxf(b.y, c.y));
        vm.z = fmaxf(a.z, fmaxf(b.z, c.z));
        vm.w = fmaxf(a.w, fmaxf(b.w, c.w));
        float vl = __shfl_up_sync(FULLM, vm.w, 1);
        float vr = __shfl_down_sync(FULLM, vm.x, 1);
        if (ledge) vl = NINF;
        if (redge) vr = NINF;
        float4 op;
        op.x = fmaxf(vm.x, fmaxf(vl,   vm.y));
        op.y = fmaxf(vm.y, fmaxf(vm.x, vm.z));
        op.z = fmaxf(vm.z, fmaxf(vm.y, vm.w));
        op.w = fmaxf(vm.w, fmaxf(vm.z, vr));

        const float4 e = L[k][h2];        // E_k row y
        float4 d;
        d.x = fmaxf(e.x - op.x, 0.0f);
        d.y = fmaxf(e.y - op.y, 0.0f);
        d.z = fmaxf(e.z - op.z, 0.0f);
        d.w = fmaxf(e.w - op.w, 0.0f);

        float* srow = ring + ((y & 15) << 7) + (lane << 2);
        float4 s;
        if (k == 0) {
            if (INIT) s = make_float4(0.0f, 0.0f, 0.0f, 0.0f);
            else      s = outok ? skel4[y * 256 + gq] : make_float4(0.0f, 0.0f, 0.0f, 0.0f);
        } else {
            s = ld4(srow);
        }
        skel_upd(s, d);
        if (k == T - 1) { if (outok) skel4[y * 256 + gq] = s; }
        else            st4(srow, s);
    }
}

// Warp-autonomous erosion tower: no block barriers at all.
// Warp w: image n = w/20, band = (w%20)/10, strip = w%10.
// Strip: loads float4 groups gq = 26*strip - 3 + lane; outputs lanes 3..28 (gq < 256).
template <int T, bool INIT, bool WRITE_E>
__global__ __launch_bounds__(128, 3)
void tower(const float* __restrict__ p0, const float* __restrict__ p1,
           float* __restrict__ eout, float* __restrict__ gskel)
{
    __shared__ float ring[4][16 * 128];

    const int wid  = threadIdx.x >> 5;
    const int lane = threadIdx.x & 31;
    const int w    = blockIdx.x * 4 + wid;
    const int n    = w / (2 * STRIPS);
    const int rem  = w % (2 * STRIPS);
    const int band = rem / STRIPS;
    const int strip = rem % STRIPS;
    const int b0 = band * BROWS, b1 = b0 + BROWS;

    const int gq = 26 * strip - 3 + lane;
    const bool loadok = (gq >= 0) && (gq < 256);
    const bool outok  = (lane >= 3) && (lane < 29) && (gq < 256);
    const bool ledge  = (gq == 0);
    const bool redge  = (gq == 255);

    const float* src;
    if (INIT) src = (n < N_IMG) ? (p0 + (size_t)n * IMG_PIX)
                                : (p1 + (size_t)(n - N_IMG) * IMG_PIX);
    else      src = p0 + (size_t)n * IMG_PIX;
    const float4* in4   = (const float4*)src;
    float4*       eout4 = (float4*)(WRITE_E ? (eout + (size_t)n * IMG_PIX) : nullptr);
    float4*       skel4 = (float4*)(gskel + (size_t)n * IMG_PIX);
    float* myring = &ring[wid][0];

    float4 L[T + 1][3];
    const float INF = __int_as_float(0x7f800000);
#pragma unroll
    for (int j = 0; j <= T; ++j)
#pragma unroll
        for (int s = 0; s < 3; ++s)
            L[j][s] = make_float4(INF, INF, INF, INF);

    const int Ys = b0 - 12;
    for (int d = 0; d < NSTEPS; d += 3) {
        do_step<T, 0, INIT, WRITE_E>(Ys + d,     L, in4, eout4, skel4, myring,
                                     lane, gq, loadok, outok, ledge, redge, b0, b1);
        do_step<T, 1, INIT, WRITE_E>(Ys + d + 1, L, in4, eout4, skel4, myring,
                                     lane, gq, loadok, outok, ledge, redge, b0, b1);
        do_step<T, 2, INIT, WRITE_E>(Ys + d + 2, L, in4, eout4, skel4, myring,
                                     lane, gq, loadok, outok, ledge, redge, b0, b1);
    }
}

__global__ void zero_sums(double* sums) {
    if (threadIdx.x < 4) sums[threadIdx.x] = 0.0;
}

// blockIdx.y = tensor t. sums[2t] += sum(skel_t * other_t); sums[2t+1] += sum(skel_t).
__global__ __launch_bounds__(256) void reduce_skel(const float* __restrict__ skel,
                                                   const float* __restrict__ target,
                                                   const float* __restrict__ inputs,
                                                   double* __restrict__ sums) {
    const int t = blockIdx.y;
    const float4* s4 = (const float4*)(skel + (size_t)t * TOTAL_F);
    const float4* o4 = (const float4*)((t == 0) ? target : inputs);
    const size_t n4 = TOTAL_F / 4;

    float acc_p = 0.0f, acc_s = 0.0f;
    const size_t stride = (size_t)gridDim.x * blockDim.x;
    for (size_t i = (size_t)blockIdx.x * blockDim.x + threadIdx.x; i < n4; i += stride) {
        const float4 a = s4[i];
        const float4 b = o4[i];
        acc_p += a.x * b.x + a.y * b.y + a.z * b.z + a.w * b.w;
        acc_s += a.x + a.y + a.z + a.w;
    }
#pragma unroll
    for (int off = 16; off > 0; off >>= 1) {
        acc_p += __shfl_down_sync(FULLM, acc_p, off);
        acc_s += __shfl_down_sync(FULLM, acc_s, off);
    }
    if ((threadIdx.x & 31) == 0) {
        atomicAdd(&sums[2 * t],     (double)acc_p);
        atomicAdd(&sums[2 * t + 1], (double)acc_s);
    }
}

__global__ void finalize_cldice(const double* __restrict__ sums, float* __restrict__ out) {
    const double tprec = (sums[0] + SMOOTH) / (sums[1] + SMOOTH);
    const double tsens = (sums[2] + SMOOTH) / (sums[3] + SMOOTH);
    out[0] = (float)(1.0 - 2.0 * (tprec * tsens) / (tprec + tsens));
}

extern "C" void kernel_launch(void* const* d_in, const int* in_sizes, int n_in,
                              void* d_out, int out_size) {
    const float* target = (const float*)d_in[0];
    const float* inputs = (const float*)d_in[1];
    float* out = (float*)d_out;

    static float* bufA = nullptr;
    static float* bufB = nullptr;
    static float* skel = nullptr;
    static double* sums = nullptr;
    if (!bufA) {
        cudaGetSymbolAddress((void**)&bufA, g_bufA);
        cudaGetSymbolAddress((void**)&bufB, g_bufB);
        cudaGetSymbolAddress((void**)&skel, g_skel);
        cudaGetSymbolAddress((void**)&sums, g_sums);
    }

    // warps: 64 images x 2 bands x 10 strips = 1280 -> 320 blocks x 4 warps
    const int NBLK = (2 * N_IMG * 2 * STRIPS) / 4;
    const dim3 block(128);

    zero_sums<<<1, 32>>>(sums);

    // Erosion tower E_0..E_26, deltas 0..25: passes T = 9, 9, 8
    tower<9, true,  true ><<<NBLK, block>>>(inputs, target, bufA, skel);
    tower<9, false, true ><<<NBLK, block>>>(bufA, nullptr, bufB, skel);
    tower<8, false, false><<<NBLK, block>>>(bufB, nullptr, nullptr, skel);

    reduce_skel<<<dim3(1024, 2), 256>>>(skel, target, inputs, sums);
    finalize_cldice<<<1, 1>>>(sums, out);
}

// round 6
// speedup vs baseline: 2.2382x; 1.2895x over previous
#include <cuda_runtime.h>
#include <cstdint>

#define IMG_W   1024
#define IMG_H   1024
#define IMG_PIX (IMG_W * IMG_H)
#define N_IMG   32
#define TOTAL_F ((size_t)N_IMG * IMG_PIX)
#define SMOOTH  1e-5
#define FULLM   0xffffffffu
#define BANDS   4
#define BROWS   (IMG_H / BANDS)       // 256
#define STRIPS  10                    // 26 useful float4 groups per strip
#define NSTEPS  279                   // >= BROWS + 22, multiple of 3

// Scratch (no cudaMalloc allowed)
__device__ float g_bufA[2 * N_IMG * IMG_PIX];
__device__ float g_bufB[2 * N_IMG * IMG_PIX];
__device__ float g_skel[2 * N_IMG * IMG_PIX];
__device__ double g_sums[4];

__device__ __forceinline__ float4 ld4(const float* p) { return *(const float4*)p; }
__device__ __forceinline__ void st4(float* p, float4 v) { *(float4*)p = v; }

__device__ __forceinline__ void skel_upd(float4& s, const float4& d) {
    s.x += fmaxf(fmaf(-s.x, d.x, d.x), 0.0f);
    s.y += fmaxf(fmaf(-s.y, d.y, d.y), 0.0f);
    s.z += fmaxf(fmaf(-s.z, d.z, d.z), 0.0f);
    s.w += fmaxf(fmaf(-s.w, d.w, d.w), 0.0f);
}

// One sweep step at row Y, ring slot U (static via unroll-3).
// Ring invariant after step Y: L[j][U] = level-j row (Y-j); (U+2)%3 = that row-1; (U+1)%3 = row-2.
// nxt  = input row Y (prefetched at step Y-1); refilled here with row Y+1.
// snxt = skel row Y-2 (prefetched at step Y-1);  refilled here with row Y-1.
template <int T, int U, bool INIT, bool WRITE_E>
__device__ __forceinline__ void do_step(
    int Y, float4 (&L)[T + 1][3], float4& nxt, float4& snxt,
    const float4* __restrict__ in4, float4* __restrict__ eout4,
    float4* __restrict__ skel4, float* __restrict__ ring,
    int lane, int gq, bool loadok, bool outok, bool ledge, bool redge,
    int b0, int b1)
{
    const float INF  = __int_as_float(0x7f800000);
    const float NINF = -INF;
    constexpr int u  = U;
    constexpr int h1 = (U + 2) % 3;
    constexpr int h2 = (U + 1) % 3;

    // Consume prefetched input row Y; prefetch row Y+1.
    L[0][u] = nxt;
    {
        const int yy = Y + 1;
        float4 v = make_float4(INF, INF, INF, INF);
        if (yy >= 0 && yy < IMG_H && loadok) v = in4[yy * 256 + gq];
        nxt = v;
    }
    // Consume prefetched skel row (Y-2); prefetch row Y-1 for next step.
    float4 scur = snxt;
    if (!INIT) {
        const int yy = Y - 1;
        float4 sv = make_float4(0.0f, 0.0f, 0.0f, 0.0f);
        if (yy >= b0 && yy < b1 && outok) sv = skel4[yy * 256 + gq];
        snxt = sv;
    }

    // Erosion levels: level j computes row r = Y - j from level j-1 rows r-1..r+1
#pragma unroll
    for (int j = 1; j <= T; ++j) {
        const int r = Y - j;
        const float4 up = L[j - 1][h2];
        const float4 ce = L[j - 1][h1];
        const float4 dn = L[j - 1][u];
        const float cl = __shfl_up_sync(FULLM, ce.w, 1);
        const float cr = __shfl_down_sync(FULLM, ce.x, 1);
        float4 o;
        o.x = fminf(fminf(fminf(up.x, dn.x), fminf(cl,   ce.y)), ce.x);
        o.y = fminf(fminf(fminf(up.y, dn.y), fminf(ce.x, ce.z)), ce.y);
        o.z = fminf(fminf(fminf(up.z, dn.z), fminf(ce.y, ce.w)), ce.z);
        o.w = fminf(fminf(fminf(up.w, dn.w), fminf(ce.z, cr  )), ce.w);
        if (r < 0 || r >= IMG_H) o = make_float4(INF, INF, INF, INF);
        L[j][u] = o;
        if (WRITE_E && j == T) {
            if (r >= b0 && r < b1 && outok) eout4[r * 256 + gq] = o;
        }
    }

    // Deltas: delta_k at row y = Y - k - 2
#pragma unroll
    for (int k = 0; k < T; ++k) {
        const int y = Y - k - 2;
        if (y < b0 || y >= b1) continue;

        float4 a = L[k + 1][h2];
        float4 b = L[k + 1][h1];
        float4 c = L[k + 1][u];
        if (y == 0)         a = make_float4(NINF, NINF, NINF, NINF);
        if (y == IMG_H - 1) c = make_float4(NINF, NINF, NINF, NINF);

        float4 vm;
        vm.x = fmaxf(a.x, fmaxf(b.x, c.x));
        vm.y = fmaxf(a.y, fmaxf(b.y, c.y));
        vm.z = fmaxf(a.z, fmaxf(b.z, c.z));
        vm.w = fmaxf(a.w, fmaxf(b.w, c.w));
        float vl = __shfl_up_sync(FULLM, vm.w, 1);
        float vr = __shfl_down_sync(FULLM, vm.x, 1);
        if (ledge) vl = NINF;
        if (redge) vr = NINF;
        float4 op;
        op.x = fmaxf(vm.x, fmaxf(vl,   vm.y));
        op.y = fmaxf(vm.y, fmaxf(vm.x, vm.z));
        op.z = fmaxf(vm.z, fmaxf(vm.y, vm.w));
        op.w = fmaxf(vm.w, fmaxf(vm.z, vr));

        const float4 e = L[k][h2];
        float4 d;
        d.x = fmaxf(e.x - op.x, 0.0f);
        d.y = fmaxf(e.y - op.y, 0.0f);
        d.z = fmaxf(e.z - op.z, 0.0f);
        d.w = fmaxf(e.w - op.w, 0.0f);

        float* srow = ring + ((y & 15) << 7) + (lane << 2);
        float4 s;
        if (k == 0) {
            if (INIT) s = make_float4(0.0f, 0.0f, 0.0f, 0.0f);
            else      s = scur;
        } else {
            s = ld4(srow);
        }
        skel_upd(s, d);
        if (k == T - 1) { if (outok) skel4[y * 256 + gq] = s; }
        else            st4(srow, s);
    }
}

// Warp-autonomous erosion tower: no block barriers.
// Warp w: image n = w/(BANDS*STRIPS), band, strip.
template <int T, bool INIT, bool WRITE_E>
__global__ __launch_bounds__(128, 3)
void tower(const float* __restrict__ p0, const float* __restrict__ p1,
           float* __restrict__ eout, float* __restrict__ gskel)
{
    __shared__ float ring[4][16 * 128];

    const int wid  = threadIdx.x >> 5;
    const int lane = threadIdx.x & 31;
    const int w    = blockIdx.x * 4 + wid;
    const int n    = w / (BANDS * STRIPS);
    const int rem  = w % (BANDS * STRIPS);
    const int band = rem / STRIPS;
    const int strip = rem % STRIPS;
    const int b0 = band * BROWS, b1 = b0 + BROWS;

    const int gq = 26 * strip - 3 + lane;
    const bool loadok = (gq >= 0) && (gq < 256);
    const bool outok  = (lane >= 3) && (lane < 29) && (gq < 256);
    const bool ledge  = (gq == 0);
    const bool redge  = (gq == 255);

    const float* src;
    if (INIT) src = (n < N_IMG) ? (p0 + (size_t)n * IMG_PIX)
                                : (p1 + (size_t)(n - N_IMG) * IMG_PIX);
    else      src = p0 + (size_t)n * IMG_PIX;
    const float4* in4   = (const float4*)src;
    float4*       eout4 = (float4*)(WRITE_E ? (eout + (size_t)n * IMG_PIX) : nullptr);
    float4*       skel4 = (float4*)(gskel + (size_t)n * IMG_PIX);
    float* myring = &ring[wid][0];

    float4 L[T + 1][3];
    const float INF = __int_as_float(0x7f800000);
#pragma unroll
    for (int j = 0; j <= T; ++j)
#pragma unroll
        for (int s = 0; s < 3; ++s)
            L[j][s] = make_float4(INF, INF, INF, INF);

    const int Ys = b0 - 12;

    // Prime prefetch registers: nxt = input row Ys; snxt unused until valid.
    float4 nxt = make_float4(INF, INF, INF, INF);
    if (Ys >= 0 && Ys < IMG_H && loadok) nxt = in4[Ys * 256 + gq];
    float4 snxt = make_float4(0.0f, 0.0f, 0.0f, 0.0f);

    for (int d = 0; d < NSTEPS; d += 3) {
        do_step<T, 0, INIT, WRITE_E>(Ys + d,     L, nxt, snxt, in4, eout4, skel4, myring,
                                     lane, gq, loadok, outok, ledge, redge, b0, b1);
        do_step<T, 1, INIT, WRITE_E>(Ys + d + 1, L, nxt, snxt, in4, eout4, skel4, myring,
                                     lane, gq, loadok, outok, ledge, redge, b0, b1);
        do_step<T, 2, INIT, WRITE_E>(Ys + d + 2, L, nxt, snxt, in4, eout4, skel4, myring,
                                     lane, gq, loadok, outok, ledge, redge, b0, b1);
    }
}

__global__ void zero_sums(double* sums) {
    if (threadIdx.x < 4) sums[threadIdx.x] = 0.0;
}

__global__ __launch_bounds__(256) void reduce_skel(const float* __restrict__ skel,
                                                   const float* __restrict__ target,
                                                   const float* __restrict__ inputs,
                                                   double* __restrict__ sums) {
    const int t = blockIdx.y;
    const float4* s4 = (const float4*)(skel + (size_t)t * TOTAL_F);
    const float4* o4 = (const float4*)((t == 0) ? target : inputs);
    const size_t n4 = TOTAL_F / 4;

    float acc_p = 0.0f, acc_s = 0.0f;
    const size_t stride = (size_t)gridDim.x * blockDim.x;
    for (size_t i = (size_t)blockIdx.x * blockDim.x + threadIdx.x; i < n4; i += stride) {
        const float4 a = s4[i];
        const float4 b = o4[i];
        acc_p += a.x * b.x + a.y * b.y + a.z * b.z + a.w * b.w;
        acc_s += a.x + a.y + a.z + a.w;
    }
#pragma unroll
    for (int off = 16; off > 0; off >>= 1) {
        acc_p += __shfl_down_sync(FULLM, acc_p, off);
        acc_s += __shfl_down_sync(FULLM, acc_s, off);
    }
    if ((threadIdx.x & 31) == 0) {
        atomicAdd(&sums[2 * t],     (double)acc_p);
        atomicAdd(&sums[2 * t + 1], (double)acc_s);
    }
}

__global__ void finalize_cldice(const double* __restrict__ sums, float* __restrict__ out) {
    const double tprec = (sums[0] + SMOOTH) / (sums[1] + SMOOTH);
    const double tsens = (sums[2] + SMOOTH) / (sums[3] + SMOOTH);
    out[0] = (float)(1.0 - 2.0 * (tprec * tsens) / (tprec + tsens));
}

extern "C" void kernel_launch(void* const* d_in, const int* in_sizes, int n_in,
                              void* d_out, int out_size) {
    const float* target = (const float*)d_in[0];
    const float* inputs = (const float*)d_in[1];
    float* out = (float*)d_out;

    static float* bufA = nullptr;
    static float* bufB = nullptr;
    static float* skel = nullptr;
    static double* sums = nullptr;
    if (!bufA) {
        cudaGetSymbolAddress((void**)&bufA, g_bufA);
        cudaGetSymbolAddress((void**)&bufB, g_bufB);
        cudaGetSymbolAddress((void**)&skel, g_skel);
        cudaGetSymbolAddress((void**)&sums, g_sums);
    }

    // warps: 64 images x 4 bands x 10 strips = 2560 -> 640 blocks x 4 warps
    const int NBLK = (2 * N_IMG * BANDS * STRIPS) / 4;
    const dim3 block(128);

    zero_sums<<<1, 32>>>(sums);

    // Erosion tower E_0..E_26, deltas 0..25: passes T = 9, 9, 8
    tower<9, true,  true ><<<NBLK, block>>>(inputs, target, bufA, skel);
    tower<9, false, true ><<<NBLK, block>>>(bufA, nullptr, bufB, skel);
    tower<8, false, false><<<NBLK, block>>>(bufB, nullptr, nullptr, skel);

    reduce_skel<<<dim3(1024, 2), 256>>>(skel, target, inputs, sums);
    finalize_cldice<<<1, 1>>>(sums, out);
}

// round 8
// speedup vs baseline: 2.4972x; 1.1157x over previous
#include <cuda_runtime.h>
#include <cstdint>

#define IMG_W   1024
#define IMG_H   1024
#define IMG_PIX (IMG_W * IMG_H)
#define N_IMG   32
#define TOTAL_F ((size_t)N_IMG * IMG_PIX)
#define SMOOTH  1e-5
#define FULLM   0xffffffffu
#define BANDS   8
#define BROWS   (IMG_H / BANDS)       // 128
#define STRIPS  10
#define NSTEPS  153                   // >= BROWS + 22, multiple of 3
#define ROWQ    (IMG_W / 4)

// Scratch (no cudaMalloc allowed)
__device__ float g_bufA[2 * N_IMG * IMG_PIX];
__device__ float g_bufB[2 * N_IMG * IMG_PIX];
__device__ float g_skel[2 * N_IMG * IMG_PIX];
__device__ double g_sums[4];

__device__ __forceinline__ float4 ld4(const float* p) { return *(const float4*)p; }
__device__ __forceinline__ void st4(float* p, float4 v) { *(float4*)p = v; }

__device__ __forceinline__ void skel_upd(float4& s, const float4& d) {
    s.x += fmaxf(fmaf(-s.x, d.x, d.x), 0.0f);
    s.y += fmaxf(fmaf(-s.y, d.y, d.y), 0.0f);
    s.z += fmaxf(fmaf(-s.z, d.z, d.z), 0.0f);
    s.w += fmaxf(fmaf(-s.w, d.w, d.w), 0.0f);
}

// One sweep step at row Y, ring slot U (compile-time).
// Ring invariant after step Y: L[j][U] = level-j row (Y-j); (U+2)%3 = that row-1; (U+1)%3 = row-2.
// nxt  = input row Y (prefetched); refilled with row Y+1.
// snxt = skel row Y-2 (prefetched); refilled with row Y-1.
template <int T, int U, bool INIT, bool WRITE_E, bool TOPB, bool BOTB>
__device__ __forceinline__ void do_step(
    int Y, float4 (&L)[T + 1][3], float4& nxt, float4& snxt,
    const float4* __restrict__ in4, float4* __restrict__ eout4,
    float4* __restrict__ skel4, float* __restrict__ ring,
    int lane, int gq, bool loadok, bool outok, bool ledge, bool redge,
    int b0, int b1)
{
    const float INF  = __int_as_float(0x7f800000);
    const float NINF = -INF;
    constexpr int u  = U;
    constexpr int h1 = (U + 2) % 3;
    constexpr int h2 = (U + 1) % 3;

    // Consume prefetched input row Y; prefetch row Y+1.
    L[0][u] = nxt;
    {
        const int yy = Y + 1;
        bool ok = loadok;
        if (TOPB) ok = ok && (yy >= 0);
        if (BOTB) ok = ok && (yy < IMG_H);
        float4 v = make_float4(INF, INF, INF, INF);
        if (ok) v = in4[yy * ROWQ + gq];
        nxt = v;
    }
    // Consume prefetched skel row (Y-2); prefetch row Y-1.
    float4 scur = snxt;
    if (!INIT) {
        const int yy = Y - 1;
        float4 sv = make_float4(0.0f, 0.0f, 0.0f, 0.0f);
        if (yy >= b0 && yy < b1 && outok) sv = skel4[yy * ROWQ + gq];
        snxt = sv;
    }

    // Erosion levels: level j computes row r = Y - j from level j-1 rows r-1..r+1
#pragma unroll
    for (int j = 1; j <= T; ++j) {
        const int r = Y - j;
        const float4 up = L[j - 1][h2];
        const float4 ce = L[j - 1][h1];
        const float4 dn = L[j - 1][u];
        const float cl = __shfl_up_sync(FULLM, ce.w, 1);
        const float cr = __shfl_down_sync(FULLM, ce.x, 1);
        float4 o;
        o.x = fminf(fminf(fminf(up.x, dn.x), fminf(cl,   ce.y)), ce.x);
        o.y = fminf(fminf(fminf(up.y, dn.y), fminf(ce.x, ce.z)), ce.y);
        o.z = fminf(fminf(fminf(up.z, dn.z), fminf(ce.y, ce.w)), ce.z);
        o.w = fminf(fminf(fminf(up.w, dn.w), fminf(ce.z, cr  )), ce.w);
        if (TOPB) { if (r < 0)      o = make_float4(INF, INF, INF, INF); }
        if (BOTB) { if (r >= IMG_H) o = make_float4(INF, INF, INF, INF); }
        L[j][u] = o;
        if (WRITE_E && j == T) {
            if (r >= b0 && r < b1 && outok) eout4[r * ROWQ + gq] = o;
        }
    }

    // Deltas: delta_k at row y = Y - k - 2
#pragma unroll
    for (int k = 0; k < T; ++k) {
        const int y = Y - k - 2;
        if (y < b0 || y >= b1) continue;

        float4 a = L[k + 1][h2];
        const float4 b = L[k + 1][h1];
        float4 c = L[k + 1][u];
        if (TOPB) { if (y == 0)         a = make_float4(NINF, NINF, NINF, NINF); }
        if (BOTB) { if (y == IMG_H - 1) c = make_float4(NINF, NINF, NINF, NINF); }

        float4 vm;
        vm.x = fmaxf(a.x, fmaxf(b.x, c.x));
        vm.y = fmaxf(a.y, fmaxf(b.y, c.y));
        vm.z = fmaxf(a.z, fmaxf(b.z, c.z));
        vm.w = fmaxf(a.w, fmaxf(b.w, c.w));
        float vl = __shfl_up_sync(FULLM, vm.w, 1);
        float vr = __shfl_down_sync(FULLM, vm.x, 1);
        if (ledge) vl = NINF;
        if (redge) vr = NINF;
        float4 op;
        op.x = fmaxf(vm.x, fmaxf(vl,   vm.y));
        op.y = fmaxf(vm.y, fmaxf(vm.x, vm.z));
        op.z = fmaxf(vm.z, fmaxf(vm.y, vm.w));
        op.w = fmaxf(vm.w, fmaxf(vm.z, vr));

        const float4 e = L[k][h2];
        float4 d;
        d.x = fmaxf(e.x - op.x, 0.0f);
        d.y = fmaxf(e.y - op.y, 0.0f);
        d.z = fmaxf(e.z - op.z, 0.0f);
        d.w = fmaxf(e.w - op.w, 0.0f);

        float* srow = ring + ((y & 15) << 7) + (lane << 2);
        float4 s;
        if (k == 0) {
            if (INIT) s = make_float4(0.0f, 0.0f, 0.0f, 0.0f);
            else      s = scur;
        } else {
            s = ld4(srow);
        }
        skel_upd(s, d);
        if (k == T - 1) { if (outok) skel4[y * ROWQ + gq] = s; }
        else            st4(srow, s);
    }
}

template <int T, bool INIT, bool WRITE_E, bool TOPB, bool BOTB>
__device__ __forceinline__ void sweep(
    const float4* __restrict__ in4, float4* __restrict__ eout4,
    float4* __restrict__ skel4, float* __restrict__ ring,
    int lane, int gq, bool loadok, bool outok, bool ledge, bool redge,
    int b0, int b1)
{
    float4 L[T + 1][3];
    const float INF = __int_as_float(0x7f800000);
#pragma unroll
    for (int j = 0; j <= T; ++j)
#pragma unroll
        for (int s = 0; s < 3; ++s)
            L[j][s] = make_float4(INF, INF, INF, INF);

    const int Ys = b0 - 12;

    float4 nxt = make_float4(INF, INF, INF, INF);
    {
        bool ok = loadok;
        if (TOPB) ok = ok && (Ys >= 0);
        if (ok) nxt = in4[Ys * ROWQ + gq];
    }
    float4 snxt = make_float4(0.0f, 0.0f, 0.0f, 0.0f);

    for (int d = 0; d < NSTEPS; d += 3) {
        do_step<T, 0, INIT, WRITE_E, TOPB, BOTB>(Ys + d,     L, nxt, snxt, in4, eout4, skel4,
                                                 ring, lane, gq, loadok, outok, ledge, redge, b0, b1);
        do_step<T, 1, INIT, WRITE_E, TOPB, BOTB>(Ys + d + 1, L, nxt, snxt, in4, eout4, skel4,
                                                 ring, lane, gq, loadok, outok, ledge, redge, b0, b1);
        do_step<T, 2, INIT, WRITE_E, TOPB, BOTB>(Ys + d + 2, L, nxt, snxt, in4, eout4, skel4,
                                                 ring, lane, gq, loadok, outok, ledge, redge, b0, b1);
    }
}

// Warp-autonomous erosion tower: no block barriers.
template <int T, bool INIT, bool WRITE_E>
__global__ __launch_bounds__(128, 3)
void tower(const float* __restrict__ p0, const float* __restrict__ p1,
           float* __restrict__ eout, float* __restrict__ gskel)
{
    __shared__ float ring[4][16 * 128];

    const int wid  = threadIdx.x >> 5;
    const int lane = threadIdx.x & 31;
    const int w    = blockIdx.x * 4 + wid;
    const int n    = w / (BANDS * STRIPS);
    const int rem  = w % (BANDS * STRIPS);
    const int band = rem / STRIPS;
    const int strip = rem % STRIPS;
    const int b0 = band * BROWS, b1 = b0 + BROWS;

    const int gq = 26 * strip - 3 + lane;
    const bool loadok = (gq >= 0) && (gq < ROWQ);
    const bool outok  = (lane >= 3) && (lane < 29) && (gq < ROWQ);
    const bool ledge  = (gq == 0);
    const bool redge  = (gq == ROWQ - 1);

    const float* src;
    if (INIT) src = (n < N_IMG) ? (p0 + (size_t)n * IMG_PIX)
                                : (p1 + (size_t)(n - N_IMG) * IMG_PIX);
    else      src = p0 + (size_t)n * IMG_PIX;
    const float4* in4   = (const float4*)src;
    float4*       eout4 = (float4*)(WRITE_E ? (eout + (size_t)n * IMG_PIX) : nullptr);
    float4*       skel4 = (float4*)(gskel + (size_t)n * IMG_PIX);
    float* myring = &ring[wid][0];

    if (band == 0)
        sweep<T, INIT, WRITE_E, true,  false>(in4, eout4, skel4, myring, lane, gq,
                                              loadok, outok, ledge, redge, b0, b1);
    else if (band == BANDS - 1)
        sweep<T, INIT, WRITE_E, false, true >(in4, eout4, skel4, myring, lane, gq,
                                              loadok, outok, ledge, redge, b0, b1);
    else
        sweep<T, INIT, WRITE_E, false, false>(in4, eout4, skel4, myring, lane, gq,
                                              loadok, outok, ledge, redge, b0, b1);
}

__global__ void zero_sums(double* sums) {
    if (threadIdx.x < 4) sums[threadIdx.x] = 0.0;
}

__global__ __launch_bounds__(256) void reduce_skel(const float* __restrict__ skel,
                                                   const float* __restrict__ target,
                                                   const float* __restrict__ inputs,
                                                   double* __restrict__ sums) {
    const int t = blockIdx.y;
    const float4* s4 = (const float4*)(skel + (size_t)t * TOTAL_F);
    const float4* o4 = (const float4*)((t == 0) ? target : inputs);
    const size_t n4 = TOTAL_F / 4;

    float acc_p = 0.0f, acc_s = 0.0f;
    const size_t stride = (size_t)gridDim.x * blockDim.x;
    for (size_t i = (size_t)blockIdx.x * blockDim.x + threadIdx.x; i < n4; i += stride) {
        const float4 a = s4[i];
        const float4 b = o4[i];
        acc_p += a.x * b.x + a.y * b.y + a.z * b.z + a.w * b.w;
        acc_s += a.x + a.y + a.z + a.w;
    }
#pragma unroll
    for (int off = 16; off > 0; off >>= 1) {
        acc_p += __shfl_down_sync(FULLM, acc_p, off);
        acc_s += __shfl_down_sync(FULLM, acc_s, off);
    }
    if ((threadIdx.x & 31) == 0) {
        atomicAdd(&sums[2 * t],     (double)acc_p);
        atomicAdd(&sums[2 * t + 1], (double)acc_s);
    }
}

__global__ void finalize_cldice(const double* __restrict__ sums, float* __restrict__ out) {
    const double tprec = (sums[0] + SMOOTH) / (sums[1] + SMOOTH);
    const double tsens = (sums[2] + SMOOTH) / (sums[3] + SMOOTH);
    out[0] = (float)(1.0 - 2.0 * (tprec * tsens) / (tprec + tsens));
}

extern "C" void kernel_launch(void* const* d_in, const int* in_sizes, int n_in,
                              void* d_out, int out_size) {
    const float* target = (const float*)d_in[0];
    const float* inputs = (const float*)d_in[1];
    float* out = (float*)d_out;

    static float* bufA = nullptr;
    static float* bufB = nullptr;
    static float* skel = nullptr;
    static double* sums = nullptr;
    if (!bufA) {
        cudaGetSymbolAddress((void**)&bufA, g_bufA);
        cudaGetSymbolAddress((void**)&bufB, g_bufB);
        cudaGetSymbolAddress((void**)&skel, g_skel);
        cudaGetSymbolAddress((void**)&sums, g_sums);
    }

    // warps: 64 images x 8 bands x 10 strips = 5120 -> 1280 blocks x 4 warps
    const int NBLK = (2 * N_IMG * BANDS * STRIPS) / 4;
    const dim3 block(128);

    zero_sums<<<1, 32>>>(sums);

    // Erosion tower E_0..E_26, deltas 0..25: passes T = 9, 9, 8
    tower<9, true,  true ><<<NBLK, block>>>(inputs, target, bufA, skel);
    tower<9, false, true ><<<NBLK, block>>>(bufA, nullptr, bufB, skel);
    tower<8, false, false><<<NBLK, block>>>(bufB, nullptr, nullptr, skel);

    reduce_skel<<<dim3(1024, 2), 256>>>(skel, target, inputs, sums);
    finalize_cldice<<<1, 1>>>(sums, out);
}